// round 5
// baseline (speedup 1.0000x reference)
#include <cuda_runtime.h>

// Problem constants
#define I_ 3
#define H_ 2048
#define O_ 2
#define R_ 2
#define S_ 4
#define G_ 7
#define B_ 32
#define T_ 512
#define ALPHA_ 0.2f
#define DECAY_ 0.8f
#define NSTD_ 0.05f

#define NTHREADS 512
#define NWARPS (NTHREADS / 32)   // 16
#define EPT 4                    // 512*4 = 2048 = H
#define NPAIR (EPT / 2)          // 2 packed pairs per thread
#define NPART (NWARPS * 4)       // 64 partials per buffer

typedef unsigned long long u64;

// ---- f32x2 packed helpers (Blackwell FFMA2 path) ----
__device__ __forceinline__ u64 pack2(float lo, float hi) {
    u64 r; asm("mov.b64 %0, {%1,%2};" : "=l"(r) : "f"(lo), "f"(hi)); return r;
}
__device__ __forceinline__ void unpack2(u64 v, float& lo, float& hi) {
    asm("mov.b64 {%0,%1}, %2;" : "=f"(lo), "=f"(hi) : "l"(v));
}
__device__ __forceinline__ u64 fma2(u64 a, u64 b, u64 c) {
    u64 d; asm("fma.rn.f32x2 %0, %1, %2, %3;" : "=l"(d) : "l"(a), "l"(b), "l"(c)); return d;
}
__device__ __forceinline__ u64 mul2(u64 a, u64 b) {
    u64 d; asm("mul.rn.f32x2 %0, %1, %2;" : "=l"(d) : "l"(a), "l"(b)); return d;
}
__device__ __forceinline__ u64 add2(u64 a, u64 b) {
    u64 d; asm("add.rn.f32x2 %0, %1, %2;" : "=l"(d) : "l"(a), "l"(b)); return d;
}
__device__ __forceinline__ float ex2f(float x) {
    float y; asm("ex2.approx.f32 %0, %1;" : "=f"(y) : "f"(x)); return y;
}
__device__ __forceinline__ float rcpf(float x) {
    float y; asm("rcp.approx.f32 %0, %1;" : "=f"(y) : "f"(x)); return y;
}

// packed tanh of a pair: th = 1 - 2/(1 + exp(2x))  (same precision class as
// __expf + __fdividef; matched rel_err 6e-6 in R1/R4)
__device__ __forceinline__ u64 tanh2(u64 hp, u64 c_2log2e, u64 c_one, u64 c_neg2) {
    u64 y = mul2(hp, c_2log2e);
    float y0, y1; unpack2(y, y0, y1);
    float e0 = ex2f(y0), e1 = ex2f(y1);
    u64 dp = add2(pack2(e0, e1), c_one);
    float d0, d1; unpack2(dp, d0, d1);
    float r0 = rcpf(d0), r1 = rcpf(d1);
    return fma2(pack2(r0, r1), c_neg2, c_one);   // 1 + (-2)*rc
}

__device__ __forceinline__ float fast_tanh(float x) {
    float e = __expf(2.0f * x);
    return 1.0f - __fdividef(2.0f, 1.0f + e);
}

__global__ __launch_bounds__(NTHREADS, 1)
void lowrank_rnn_kernel(const float* __restrict__ input,   // (B,T,I)
                        const float* __restrict__ noise,   // (B,T,H)
                        const float* __restrict__ wi,      // (I,S,G)
                        const float* __restrict__ unitwi,  // (I,S,1)
                        const float* __restrict__ m,       // (R,S,G)
                        const float* __restrict__ n,       // (R,S,G)
                        const float* __restrict__ unitm,   // (R,S,1)
                        const float* __restrict__ unitn,   // (R,S,1)
                        const float* __restrict__ wo,      // (O,S,G)
                        const float* __restrict__ h0,      // (S,G)
                        const float* __restrict__ unith0,  // (S,1)
                        const float* __restrict__ bias,    // (S,1)
                        const float* __restrict__ gb,      // (G,H)
                        const float* __restrict__ uv,      // (1,H)
                        const float* __restrict__ sup,     // (S,H)
                        float* __restrict__ out)           // out(B,T,O) ++ traj(B,T,H)
{
    const int b    = blockIdx.x;
    const int tid  = threadIdx.x;
    const int lane = tid & 31;
    const int warp = tid >> 5;
    const unsigned FULL = 0xffffffffu;

    __shared__ float s_red[2 * NPART];

    // ------------------------------------------------------------------
    // Phase 1: per-element effective weights (scalar, one-time), then pack.
    // ------------------------------------------------------------------
    float f_h[EPT];
    float f_m0[EPT], f_m1[EPT], f_n0[EPT], f_n1[EPT];
    float f_wo0[EPT], f_wo1[EPT], f_bias[EPT];
    float f_wi0[EPT], f_wi1[EPT], f_wi2[EPT];

#pragma unroll
    for (int e = 0; e < EPT; e++) {
        const int hidx = tid * EPT + e;
        float gvec[G_];
#pragma unroll
        for (int g = 0; g < G_; g++) gvec[g] = gb[g * H_ + hidx];
        const float uvh = uv[hidx];

        float awi0 = 0.f, awi1 = 0.f, awi2 = 0.f;
        float am0 = 0.f, am1 = 0.f, an0 = 0.f, an1 = 0.f;
        float awo0 = 0.f, awo1 = 0.f, ah0 = 0.f, ab = 0.f;

#pragma unroll
        for (int s = 0; s < S_; s++) {
            const float su = sup[s * H_ + hidx];

            float d0 = 0.f, d1 = 0.f, d2 = 0.f;
#pragma unroll
            for (int g = 0; g < G_; g++) {
                d0 += wi[(0 * S_ + s) * G_ + g] * gvec[g];
                d1 += wi[(1 * S_ + s) * G_ + g] * gvec[g];
                d2 += wi[(2 * S_ + s) * G_ + g] * gvec[g];
            }
            awi0 += (d0 + unitwi[0 * S_ + s] * uvh) * su;
            awi1 += (d1 + unitwi[1 * S_ + s] * uvh) * su;
            awi2 += (d2 + unitwi[2 * S_ + s] * uvh) * su;

            float dm0 = 0.f, dm1 = 0.f, dn0 = 0.f, dn1 = 0.f;
#pragma unroll
            for (int g = 0; g < G_; g++) {
                dm0 += m[(0 * S_ + s) * G_ + g] * gvec[g];
                dm1 += m[(1 * S_ + s) * G_ + g] * gvec[g];
                dn0 += n[(0 * S_ + s) * G_ + g] * gvec[g];
                dn1 += n[(1 * S_ + s) * G_ + g] * gvec[g];
            }
            am0 += (dm0 + unitm[0 * S_ + s] * uvh) * su;
            am1 += (dm1 + unitm[1 * S_ + s] * uvh) * su;
            an0 += (dn0 + unitn[0 * S_ + s] * uvh) * su;
            an1 += (dn1 + unitn[1 * S_ + s] * uvh) * su;

            float do0 = 0.f, do1 = 0.f, dh = 0.f;
#pragma unroll
            for (int g = 0; g < G_; g++) {
                do0 += wo[(0 * S_ + s) * G_ + g] * gvec[g];
                do1 += wo[(1 * S_ + s) * G_ + g] * gvec[g];
                dh  += h0[s * G_ + g] * gvec[g];
            }
            awo0 += do0 * su;
            awo1 += do1 * su;
            ah0  += dh * su + unith0[s] * uvh * su;
            ab   += bias[s] * uvh * su;
        }
        f_h[e]   = ah0;
        f_m0[e]  = ALPHA_ * am0;  f_m1[e]  = ALPHA_ * am1;
        f_n0[e]  = an0;           f_n1[e]  = an1;
        f_wo0[e] = awo0;          f_wo1[e] = awo1;
        f_bias[e] = ab;
        f_wi0[e] = ALPHA_ * awi0; f_wi1[e] = ALPHA_ * awi1;
        f_wi2[e] = ALPHA_ * awi2;
    }

    // Packed state/constants
    u64 hpack[NPAIR];                      // (h[2p], h[2p+1])
    u64 p_m0[NPAIR], p_m1[NPAIR];          // element pairs
    u64 p_wi0[NPAIR], p_wi1[NPAIR], p_wi2[NPAIR], p_bias[NPAIR];
    u64 p_n01[EPT], p_wo01[EPT];           // per-element channel pairs
#pragma unroll
    for (int p = 0; p < NPAIR; p++) {
        hpack[p]  = pack2(f_h[2 * p],   f_h[2 * p + 1]);
        p_m0[p]   = pack2(f_m0[2 * p],  f_m0[2 * p + 1]);
        p_m1[p]   = pack2(f_m1[2 * p],  f_m1[2 * p + 1]);
        p_wi0[p]  = pack2(f_wi0[2 * p], f_wi0[2 * p + 1]);
        p_wi1[p]  = pack2(f_wi1[2 * p], f_wi1[2 * p + 1]);
        p_wi2[p]  = pack2(f_wi2[2 * p], f_wi2[2 * p + 1]);
        p_bias[p] = pack2(f_bias[2 * p], f_bias[2 * p + 1]);
    }
#pragma unroll
    for (int e = 0; e < EPT; e++) {
        p_n01[e]  = pack2(f_n0[e],  f_n1[e]);
        p_wo01[e] = pack2(f_wo0[e], f_wo1[e]);
    }
    const u64 C_DECAY2  = pack2(DECAY_, DECAY_);
    const u64 C_NSTD2   = pack2(NSTD_, NSTD_);
    const u64 C_2LOG2E2 = pack2(2.8853900817779268f, 2.8853900817779268f);
    const u64 C_ONE2    = pack2(1.0f, 1.0f);
    const u64 C_NEG22   = pack2(-2.0f, -2.0f);

    // ------------------------------------------------------------------
    // Phase 2: recurrence (pipelined as in R4).
    //   Loop-top invariant: prA=(Σr·n0, Σr·n1), prB=(Σr·wo0, Σr·wo1) of
    //   r_t = tanh(h_t); hpack = h_t.
    //   Iter t: reduce -> Sn_t (+ out[t-1]); store traj[t-1] (=h_t) in the
    //   stage-A shadow; h_{t+1} = 0.8h + bias + z + x·wi + Sn·m; new pr.
    // ------------------------------------------------------------------
    const float* zb = noise + (size_t)b * T_ * H_;
    const float* xb = input + (size_t)b * T_ * I_;
    float* outp  = out + (size_t)b * T_ * O_;
    float* trajp = out + (size_t)B_ * T_ * O_ + (size_t)b * T_ * H_;

    // Initial pr from r0 = tanh(h0)
    u64 prA = pack2(0.f, 0.f), prB = pack2(0.f, 0.f);
#pragma unroll
    for (int p = 0; p < NPAIR; p++) {
        u64 th = tanh2(hpack[p], C_2LOG2E2, C_ONE2, C_NEG22);
        float r0, r1; unpack2(th, r0, r1);
        prA = fma2(pack2(r0, r0), p_n01[2 * p],      prA);
        prB = fma2(pack2(r0, r0), p_wo01[2 * p],     prB);
        prA = fma2(pack2(r1, r1), p_n01[2 * p + 1],  prA);
        prB = fma2(pack2(r1, r1), p_wo01[2 * p + 1], prB);
    }

    // Prefetch noise / input two steps ahead
    float4 z0 = *(const float4*)(zb + 0 * (size_t)H_ + tid * 4);
    float4 z1 = *(const float4*)(zb + 1 * (size_t)H_ + tid * 4);
    float xA0 = xb[0], xA1 = xb[1], xA2 = xb[2];
    float xB0 = xb[3], xB1 = xb[4], xB2 = xb[5];

    for (int t = 0; t < T_; t++) {
        const int buf = t & 1;

        // ---- stage A: warp-level folded reduce (6 SHFL) ----
        {
            float px, py, pz, pw;
            unpack2(prA, px, py);
            unpack2(prB, pz, pw);
            const bool k1 = !(lane & 1);
            float sA = k1 ? pz : px;
            float rA = __shfl_xor_sync(FULL, sA, 1);
            float v0 = (k1 ? px : pz) + rA;
            float sB = k1 ? pw : py;
            float rB = __shfl_xor_sync(FULL, sB, 1);
            float v1 = (k1 ? py : pw) + rB;
            const bool k2 = !(lane & 2);
            float sC = k2 ? v1 : v0;
            float rC = __shfl_xor_sync(FULL, sC, 2);
            float v  = (k2 ? v0 : v1) + rC;
            v += __shfl_xor_sync(FULL, v, 4);
            v += __shfl_xor_sync(FULL, v, 8);
            v += __shfl_xor_sync(FULL, v, 16);
            if (lane < 4) s_red[buf * NPART + warp * 4 + lane] = v;
        }

        // ---- stage-A shadow: traj[t-1] store + z/x prefetch + zh-part ----
        if (t > 0) {
            float h0f, h1f, h2f, h3f;
            unpack2(hpack[0], h0f, h1f);
            unpack2(hpack[1], h2f, h3f);
            *(float4*)(trajp + (size_t)(t - 1) * H_ + tid * 4) =
                make_float4(h0f, h1f, h2f, h3f);
        }
        const int tp = (t + 2 < T_) ? (t + 2) : (T_ - 1);
        float4 z2 = *(const float4*)(zb + (size_t)tp * H_ + tid * 4);
        const float xC0 = xb[tp * I_ + 0];
        const float xC1 = xb[tp * I_ + 1];
        const float xC2 = xb[tp * I_ + 2];

        u64 hb[NPAIR];
        {
            u64 zp0 = pack2(z0.x, z0.y);
            u64 zp1 = pack2(z0.z, z0.w);
            hb[0] = fma2(hpack[0], C_DECAY2, p_bias[0]);
            hb[0] = fma2(zp0, C_NSTD2, hb[0]);
            hb[1] = fma2(hpack[1], C_DECAY2, p_bias[1]);
            hb[1] = fma2(zp1, C_NSTD2, hb[1]);
        }

        __syncthreads();

        // ---- post-barrier: x·wi FFMA2s issue during stage-C SHFL latency ----
        u64 xA0p = pack2(xA0, xA0);
        u64 xA1p = pack2(xA1, xA1);
        u64 xA2p = pack2(xA2, xA2);
#pragma unroll
        for (int p = 0; p < NPAIR; p++) {
            hb[p] = fma2(xA0p, p_wi0[p], hb[p]);
            hb[p] = fma2(xA1p, p_wi1[p], hb[p]);
            hb[p] = fma2(xA2p, p_wi2[p], hb[p]);
        }

        // ---- stage C: cross-warp reduce ----
        float Sn0, Sn1;
        {
            float u = s_red[buf * NPART + lane] + s_red[buf * NPART + 32 + lane];
            u += __shfl_xor_sync(FULL, u, 4);
            u += __shfl_xor_sync(FULL, u, 8);
            u += __shfl_xor_sync(FULL, u, 16);
            // lane&3: 0 -> n0, 1 -> wo0, 2 -> n1, 3 -> wo1
            Sn0 = __shfl_sync(FULL, u, 0);
            Sn1 = __shfl_sync(FULL, u, 2);
            if (warp == 0 && t > 0) {
                if (lane == 1) outp[(t - 1) * O_ + 0] = u;
                if (lane == 3) outp[(t - 1) * O_ + 1] = u;
            }
        }

        // ---- stage D: h_{t+1}, tanh, next pr ----
        u64 Sn0p = pack2(Sn0, Sn0);
        u64 Sn1p = pack2(Sn1, Sn1);
        prA = pack2(0.f, 0.f);
        prB = pack2(0.f, 0.f);
#pragma unroll
        for (int p = 0; p < NPAIR; p++) {
            u64 h = fma2(Sn0p, p_m0[p], hb[p]);
            h = fma2(Sn1p, p_m1[p], h);
            hpack[p] = h;
            u64 th = tanh2(h, C_2LOG2E2, C_ONE2, C_NEG22);
            float r0, r1; unpack2(th, r0, r1);
            prA = fma2(pack2(r0, r0), p_n01[2 * p],      prA);
            prB = fma2(pack2(r0, r0), p_wo01[2 * p],     prB);
            prA = fma2(pack2(r1, r1), p_n01[2 * p + 1],  prA);
            prB = fma2(pack2(r1, r1), p_wo01[2 * p + 1], prB);
        }

        z0 = z1; z1 = z2;
        xA0 = xB0; xA1 = xB1; xA2 = xB2;
        xB0 = xC0; xB1 = xC1; xB2 = xC2;
    }

    // ---- epilogue: traj[T-1] and out[T-1] ----
    {
        float h0f, h1f, h2f, h3f;
        unpack2(hpack[0], h0f, h1f);
        unpack2(hpack[1], h2f, h3f);
        *(float4*)(trajp + (size_t)(T_ - 1) * H_ + tid * 4) =
            make_float4(h0f, h1f, h2f, h3f);

        const int buf = T_ & 1;
        float px, py, pz, pw;
        unpack2(prA, px, py);
        unpack2(prB, pz, pw);
        const bool k1 = !(lane & 1);
        float sA = k1 ? pz : px;
        float rA = __shfl_xor_sync(FULL, sA, 1);
        float v0 = (k1 ? px : pz) + rA;
        float sB = k1 ? pw : py;
        float rB = __shfl_xor_sync(FULL, sB, 1);
        float v1 = (k1 ? py : pw) + rB;
        const bool k2 = !(lane & 2);
        float sC = k2 ? v1 : v0;
        float rC = __shfl_xor_sync(FULL, sC, 2);
        float v  = (k2 ? v0 : v1) + rC;
        v += __shfl_xor_sync(FULL, v, 4);
        v += __shfl_xor_sync(FULL, v, 8);
        v += __shfl_xor_sync(FULL, v, 16);
        if (lane < 4) s_red[buf * NPART + warp * 4 + lane] = v;
        __syncthreads();
        if (warp == 0) {
            float u = s_red[buf * NPART + lane] + s_red[buf * NPART + 32 + lane];
            u += __shfl_xor_sync(FULL, u, 4);
            u += __shfl_xor_sync(FULL, u, 8);
            u += __shfl_xor_sync(FULL, u, 16);
            if (lane == 1) outp[(T_ - 1) * O_ + 0] = u;
            if (lane == 3) outp[(T_ - 1) * O_ + 1] = u;
        }
    }
}

extern "C" void kernel_launch(void* const* d_in, const int* in_sizes, int n_in,
                              void* d_out, int out_size) {
    (void)in_sizes; (void)n_in; (void)out_size;
    const float* input    = (const float*)d_in[0];
    const float* noise    = (const float*)d_in[1];
    const float* wi       = (const float*)d_in[2];
    const float* unitwi   = (const float*)d_in[3];
    const float* m        = (const float*)d_in[4];
    const float* n        = (const float*)d_in[5];
    const float* unitm    = (const float*)d_in[6];
    const float* unitn    = (const float*)d_in[7];
    const float* wo       = (const float*)d_in[8];
    const float* h0       = (const float*)d_in[9];
    const float* unith0   = (const float*)d_in[10];
    const float* bias     = (const float*)d_in[11];
    const float* gb       = (const float*)d_in[12];
    const float* uv       = (const float*)d_in[13];
    const float* sup      = (const float*)d_in[14];
    float* out            = (float*)d_out;

    lowrank_rnn_kernel<<<B_, NTHREADS>>>(input, noise, wi, unitwi, m, n, unitm,
                                         unitn, wo, h0, unith0, bias, gb, uv,
                                         sup, out);
}

// round 6
// speedup vs baseline: 1.0282x; 1.0282x over previous
#include <cuda_runtime.h>

// Problem constants
#define I_ 3
#define H_ 2048
#define O_ 2
#define R_ 2
#define S_ 4
#define G_ 7
#define B_ 32
#define T_ 512
#define ALPHA_ 0.2f
#define DECAY_ 0.8f
#define NSTD_ 0.05f

#define NTHREADS 512
#define NWARPS (NTHREADS / 32)   // 16
#define EPT 2                    // 512*2 = 1024 = H/2 per CTA
#define HHALF 1024
#define NPART (NWARPS * 4)       // 64 partials per buffer

typedef unsigned long long u64;

// ---- f32x2 packed helpers ----
__device__ __forceinline__ u64 pack2(float lo, float hi) {
    u64 r; asm("mov.b64 %0, {%1,%2};" : "=l"(r) : "f"(lo), "f"(hi)); return r;
}
__device__ __forceinline__ void unpack2(u64 v, float& lo, float& hi) {
    asm("mov.b64 {%0,%1}, %2;" : "=f"(lo), "=f"(hi) : "l"(v));
}
__device__ __forceinline__ u64 fma2(u64 a, u64 b, u64 c) {
    u64 d; asm("fma.rn.f32x2 %0, %1, %2, %3;" : "=l"(d) : "l"(a), "l"(b), "l"(c)); return d;
}
__device__ __forceinline__ u64 mul2(u64 a, u64 b) {
    u64 d; asm("mul.rn.f32x2 %0, %1, %2;" : "=l"(d) : "l"(a), "l"(b)); return d;
}
__device__ __forceinline__ u64 add2(u64 a, u64 b) {
    u64 d; asm("add.rn.f32x2 %0, %1, %2;" : "=l"(d) : "l"(a), "l"(b)); return d;
}
__device__ __forceinline__ float ex2f(float x) {
    float y; asm("ex2.approx.f32 %0, %1;" : "=f"(y) : "f"(x)); return y;
}
__device__ __forceinline__ float rcpf(float x) {
    float y; asm("rcp.approx.f32 %0, %1;" : "=f"(y) : "f"(x)); return y;
}
// packed tanh: 1 - 2/(1+exp(2x)) — same precision class as R4/R5 (rel_err 6e-6)
__device__ __forceinline__ u64 tanh2(u64 hp, u64 c_2log2e, u64 c_one, u64 c_neg2) {
    u64 y = mul2(hp, c_2log2e);
    float y0, y1; unpack2(y, y0, y1);
    float e0 = ex2f(y0), e1 = ex2f(y1);
    u64 dp = add2(pack2(e0, e1), c_one);
    float d0, d1; unpack2(dp, d0, d1);
    float r0 = rcpf(d0), r1 = rcpf(d1);
    return fma2(pack2(r0, r1), c_neg2, c_one);
}

// ---- cluster / mbarrier helpers ----
__device__ __forceinline__ unsigned sm32(const void* p) {
    return (unsigned)__cvta_generic_to_shared(const_cast<void*>(p));
}
__device__ __forceinline__ unsigned mapa_u32(unsigned addr, unsigned rank) {
    unsigned r;
    asm("mapa.shared::cluster.u32 %0, %1, %2;" : "=r"(r) : "r"(addr), "r"(rank));
    return r;
}
__device__ __forceinline__ void mbar_init(unsigned mbar, unsigned cnt) {
    asm volatile("mbarrier.init.shared.b64 [%0], %1;" :: "r"(mbar), "r"(cnt) : "memory");
}
__device__ __forceinline__ void mbar_expect_tx(unsigned mbar, unsigned bytes) {
    asm volatile("mbarrier.arrive.expect_tx.shared.b64 _, [%0], %1;"
                 :: "r"(mbar), "r"(bytes) : "memory");
}
__device__ __forceinline__ void mbar_wait(unsigned mbar, unsigned phase) {
    asm volatile(
        "{\n\t.reg .pred P;\n\t"
        "WL_%=:\n\t"
        "mbarrier.try_wait.parity.shared.b64 P, [%0], %1;\n\t"
        "@P bra.uni WD_%=;\n\t"
        "bra.uni WL_%=;\n\t"
        "WD_%=:\n\t}"
        :: "r"(mbar), "r"(phase) : "memory");
}
__device__ __forceinline__ void st_async_f32(unsigned raddr, float v, unsigned rmbar) {
    asm volatile(
        "st.async.shared::cluster.mbarrier::complete_tx::bytes.b32 [%0], %1, [%2];"
        :: "r"(raddr), "r"(__float_as_uint(v)), "r"(rmbar) : "memory");
}
__device__ __forceinline__ void cluster_sync() {
    asm volatile("barrier.cluster.arrive.aligned;" ::: "memory");
    asm volatile("barrier.cluster.wait.aligned;" ::: "memory");
}

__global__ __launch_bounds__(NTHREADS, 1) __cluster_dims__(2, 1, 1)
void lowrank_rnn_kernel(const float* __restrict__ input,   // (B,T,I)
                        const float* __restrict__ noise,   // (B,T,H)
                        const float* __restrict__ wi,      // (I,S,G)
                        const float* __restrict__ unitwi,  // (I,S,1)
                        const float* __restrict__ m,       // (R,S,G)
                        const float* __restrict__ n,       // (R,S,G)
                        const float* __restrict__ unitm,   // (R,S,1)
                        const float* __restrict__ unitn,   // (R,S,1)
                        const float* __restrict__ wo,      // (O,S,G)
                        const float* __restrict__ h0,      // (S,G)
                        const float* __restrict__ unith0,  // (S,1)
                        const float* __restrict__ bias,    // (S,1)
                        const float* __restrict__ gb,      // (G,H)
                        const float* __restrict__ uv,      // (1,H)
                        const float* __restrict__ sup,     // (S,H)
                        float* __restrict__ out)           // out(B,T,O) ++ traj(B,T,H)
{
    const int b    = blockIdx.x >> 1;
    const unsigned rank = blockIdx.x & 1;
    const unsigned peer = rank ^ 1;
    const int tid  = threadIdx.x;
    const int lane = tid & 31;
    const int warp = tid >> 5;
    const unsigned FULL = 0xffffffffu;

    __shared__ float  s_red[2][NPART];
    __shared__ float4 s_rem[2];                // peer-written partials
    __shared__ u64    s_mbar[2];

    const unsigned red_base  = sm32(&s_red[0][0]);
    const unsigned rem_base  = sm32(&s_rem[0]);
    const unsigned mbar_base = sm32(&s_mbar[0]);

    if (tid == 0) {
        mbar_init(mbar_base, 1);
        mbar_init(mbar_base + 8, 1);
    }
    __syncthreads();
    cluster_sync();   // peers' mbarriers initialized before any st.async

    // peer addresses (4 send slots per buffer + peer mbars)
    const unsigned p_rem0  = mapa_u32(rem_base + (unsigned)(lane & 3) * 4u, peer);
    const unsigned p_rem1  = mapa_u32(rem_base + 16u + (unsigned)(lane & 3) * 4u, peer);
    const unsigned p_mbar0 = mapa_u32(mbar_base, peer);
    const unsigned p_mbar1 = mapa_u32(mbar_base + 8, peer);

    // ------------------------------------------------------------------
    // Phase 1: per-element effective weights (this CTA's H-half).
    // ------------------------------------------------------------------
    float f_h[EPT];
    float f_m0[EPT], f_m1[EPT], f_n0[EPT], f_n1[EPT];
    float f_wo0[EPT], f_wo1[EPT], f_bias[EPT];
    float f_wi0[EPT], f_wi1[EPT], f_wi2[EPT];

#pragma unroll
    for (int e = 0; e < EPT; e++) {
        const int hidx = rank * HHALF + tid * EPT + e;
        float gvec[G_];
#pragma unroll
        for (int g = 0; g < G_; g++) gvec[g] = gb[g * H_ + hidx];
        const float uvh = uv[hidx];

        float awi0 = 0.f, awi1 = 0.f, awi2 = 0.f;
        float am0 = 0.f, am1 = 0.f, an0 = 0.f, an1 = 0.f;
        float awo0 = 0.f, awo1 = 0.f, ah0 = 0.f, ab = 0.f;

#pragma unroll
        for (int s = 0; s < S_; s++) {
            const float su = sup[s * H_ + hidx];

            float d0 = 0.f, d1 = 0.f, d2 = 0.f;
#pragma unroll
            for (int g = 0; g < G_; g++) {
                d0 += wi[(0 * S_ + s) * G_ + g] * gvec[g];
                d1 += wi[(1 * S_ + s) * G_ + g] * gvec[g];
                d2 += wi[(2 * S_ + s) * G_ + g] * gvec[g];
            }
            awi0 += (d0 + unitwi[0 * S_ + s] * uvh) * su;
            awi1 += (d1 + unitwi[1 * S_ + s] * uvh) * su;
            awi2 += (d2 + unitwi[2 * S_ + s] * uvh) * su;

            float dm0 = 0.f, dm1 = 0.f, dn0 = 0.f, dn1 = 0.f;
#pragma unroll
            for (int g = 0; g < G_; g++) {
                dm0 += m[(0 * S_ + s) * G_ + g] * gvec[g];
                dm1 += m[(1 * S_ + s) * G_ + g] * gvec[g];
                dn0 += n[(0 * S_ + s) * G_ + g] * gvec[g];
                dn1 += n[(1 * S_ + s) * G_ + g] * gvec[g];
            }
            am0 += (dm0 + unitm[0 * S_ + s] * uvh) * su;
            am1 += (dm1 + unitm[1 * S_ + s] * uvh) * su;
            an0 += (dn0 + unitn[0 * S_ + s] * uvh) * su;
            an1 += (dn1 + unitn[1 * S_ + s] * uvh) * su;

            float do0 = 0.f, do1 = 0.f, dh = 0.f;
#pragma unroll
            for (int g = 0; g < G_; g++) {
                do0 += wo[(0 * S_ + s) * G_ + g] * gvec[g];
                do1 += wo[(1 * S_ + s) * G_ + g] * gvec[g];
                dh  += h0[s * G_ + g] * gvec[g];
            }
            awo0 += do0 * su;
            awo1 += do1 * su;
            ah0  += dh * su + unith0[s] * uvh * su;
            ab   += bias[s] * uvh * su;
        }
        f_h[e]   = ah0;
        f_m0[e]  = ALPHA_ * am0;  f_m1[e]  = ALPHA_ * am1;
        f_n0[e]  = an0;           f_n1[e]  = an1;
        f_wo0[e] = awo0;          f_wo1[e] = awo1;
        f_bias[e] = ab;
        f_wi0[e] = ALPHA_ * awi0; f_wi1[e] = ALPHA_ * awi1;
        f_wi2[e] = ALPHA_ * awi2;
    }

    // Packed state/constants (one pair per thread)
    u64 hpack  = pack2(f_h[0], f_h[1]);
    u64 p_m0   = pack2(f_m0[0], f_m0[1]);
    u64 p_m1   = pack2(f_m1[0], f_m1[1]);
    u64 p_wi0  = pack2(f_wi0[0], f_wi0[1]);
    u64 p_wi1  = pack2(f_wi1[0], f_wi1[1]);
    u64 p_wi2  = pack2(f_wi2[0], f_wi2[1]);
    u64 p_bias = pack2(f_bias[0], f_bias[1]);
    u64 p_n01_0  = pack2(f_n0[0],  f_n1[0]);
    u64 p_n01_1  = pack2(f_n0[1],  f_n1[1]);
    u64 p_wo01_0 = pack2(f_wo0[0], f_wo0[1] * 0.f + f_wo1[0]);  // (wo0[0], wo1[0])
    u64 p_wo01_1 = pack2(f_wo0[1], f_wo1[1]);                   // (wo0[1], wo1[1])
    const u64 C_DECAY2  = pack2(DECAY_, DECAY_);
    const u64 C_NSTD2   = pack2(NSTD_, NSTD_);
    const u64 C_2LOG2E2 = pack2(2.8853900817779268f, 2.8853900817779268f);
    const u64 C_ONE2    = pack2(1.0f, 1.0f);
    const u64 C_NEG22   = pack2(-2.0f, -2.0f);

    // ------------------------------------------------------------------
    // Phase 2: recurrence. Per iter: local 2-level reduce -> 4 partials;
    // exchange with peer CTA via st.async + mbarrier; combine -> Sn.
    // ------------------------------------------------------------------
    const float* zb = noise + (size_t)b * T_ * H_ + rank * HHALF;
    const float* xb = input + (size_t)b * T_ * I_;
    float* outp  = out + (size_t)b * T_ * O_;
    float* trajp = out + (size_t)B_ * T_ * O_ + (size_t)b * T_ * H_ + rank * HHALF;

    // Initial pr from r0 = tanh(h0): channels (x=n0, y=n1) in prA, (z=wo0, w=wo1) in prB
    u64 prA, prB;
    {
        u64 th = tanh2(hpack, C_2LOG2E2, C_ONE2, C_NEG22);
        float r0, r1; unpack2(th, r0, r1);
        u64 r0p = pack2(r0, r0), r1p = pack2(r1, r1);
        prA = fma2(r1p, p_n01_1,  mul2(r0p, p_n01_0));
        prB = fma2(r1p, p_wo01_1, mul2(r0p, p_wo01_0));
    }

    // Prefetch noise / input two steps ahead
    float2 z0 = *(const float2*)(zb + 0 * (size_t)H_ + tid * EPT);
    float2 z1 = *(const float2*)(zb + 1 * (size_t)H_ + tid * EPT);
    float xA0 = xb[0], xA1 = xb[1], xA2 = xb[2];
    float xB0 = xb[3], xB1 = xb[4], xB2 = xb[5];

    unsigned ph0 = 0, ph1 = 0;

    for (int t = 0; t < T_; t++) {
        const int buf = t & 1;
        if (tid == 0) mbar_expect_tx(mbar_base + (unsigned)buf * 8u, 16u);

        // ---- stage A: warp-level folded reduce (6 SHFL) ----
        {
            float px, py, pz, pw;
            unpack2(prA, px, py);
            unpack2(prB, pz, pw);
            const bool k1 = !(lane & 1);
            float sA = k1 ? pz : px;
            float rA = __shfl_xor_sync(FULL, sA, 1);
            float v0 = (k1 ? px : pz) + rA;
            float sB = k1 ? pw : py;
            float rB = __shfl_xor_sync(FULL, sB, 1);
            float v1 = (k1 ? py : pw) + rB;
            const bool k2 = !(lane & 2);
            float sC = k2 ? v1 : v0;
            float rC = __shfl_xor_sync(FULL, sC, 2);
            float v  = (k2 ? v0 : v1) + rC;
            v += __shfl_xor_sync(FULL, v, 4);
            v += __shfl_xor_sync(FULL, v, 8);
            v += __shfl_xor_sync(FULL, v, 16);
            if (lane < 4) s_red[buf][warp * 4 + lane] = v;
        }

        // ---- shadow: traj store, prefetch, base (decay+bias+noise) ----
        if (t > 0) {
            float h0f, h1f; unpack2(hpack, h0f, h1f);
            *(float2*)(trajp + (size_t)(t - 1) * H_ + tid * EPT) =
                make_float2(h0f, h1f);
        }
        const int tp = (t + 2 < T_) ? (t + 2) : (T_ - 1);
        float2 z2 = *(const float2*)(zb + (size_t)tp * H_ + tid * EPT);
        const float xC0 = xb[tp * I_ + 0];
        const float xC1 = xb[tp * I_ + 1];
        const float xC2 = xb[tp * I_ + 2];

        u64 hb = fma2(hpack, C_DECAY2, p_bias);
        hb = fma2(pack2(z0.x, z0.y), C_NSTD2, hb);

        __syncthreads();

        // ---- stage C: cross-warp local reduce ----
        float u;
        {
            u = s_red[buf][lane] + s_red[buf][32 + lane];
            u += __shfl_xor_sync(FULL, u, 4);
            u += __shfl_xor_sync(FULL, u, 8);
            u += __shfl_xor_sync(FULL, u, 16);
            // lane&3: 0 -> n0, 1 -> wo0, 2 -> n1, 3 -> wo1 (CTA-local partials)
        }

        // ---- send our 4 partials to the peer (DSMEM, async) ----
        if (warp == 0 && lane < 4) {
            st_async_f32(buf ? p_rem1 : p_rem0, u, buf ? p_mbar1 : p_mbar0);
        }

        // ---- overlap DSMEM flight with x·wi FMAs ----
        hb = fma2(pack2(xA0, xA0), p_wi0, hb);
        hb = fma2(pack2(xA1, xA1), p_wi1, hb);
        hb = fma2(pack2(xA2, xA2), p_wi2, hb);

        // ---- wait for peer's partials, combine ----
        mbar_wait(mbar_base + (unsigned)buf * 8u, buf ? ph1 : ph0);
        if (buf) ph1 ^= 1u; else ph0 ^= 1u;
        float4 rem = s_rem[buf];
        float Sn0 = __shfl_sync(FULL, u, 0) + rem.x;
        float Sn1 = __shfl_sync(FULL, u, 2) + rem.z;
        if (rank == 0 && warp == 0 && t > 0) {
            if (lane == 1) outp[(t - 1) * O_ + 0] = u + rem.y;
            if (lane == 3) outp[(t - 1) * O_ + 1] = u + rem.w;
        }

        // ---- stage D: h_{t+1}, tanh, next pr ----
        u64 h = fma2(pack2(Sn0, Sn0), p_m0, hb);
        h = fma2(pack2(Sn1, Sn1), p_m1, h);
        hpack = h;
        u64 th = tanh2(h, C_2LOG2E2, C_ONE2, C_NEG22);
        float r0, r1; unpack2(th, r0, r1);
        u64 r0p = pack2(r0, r0), r1p = pack2(r1, r1);
        prA = fma2(r1p, p_n01_1,  mul2(r0p, p_n01_0));
        prB = fma2(r1p, p_wo01_1, mul2(r0p, p_wo01_0));

        z0 = z1; z1 = z2;
        xA0 = xB0; xA1 = xB1; xA2 = xB2;
        xB0 = xC0; xB1 = xC1; xB2 = xC2;
    }

    // ---- epilogue: traj[T-1]; one more exchange for out[T-1] ----
    {
        float h0f, h1f; unpack2(hpack, h0f, h1f);
        *(float2*)(trajp + (size_t)(T_ - 1) * H_ + tid * EPT) =
            make_float2(h0f, h1f);

        const int buf = T_ & 1;   // 0
        if (tid == 0) mbar_expect_tx(mbar_base + (unsigned)buf * 8u, 16u);
        float px, py, pz, pw;
        unpack2(prA, px, py);
        unpack2(prB, pz, pw);
        const bool k1 = !(lane & 1);
        float sA = k1 ? pz : px;
        float rA = __shfl_xor_sync(FULL, sA, 1);
        float v0 = (k1 ? px : pz) + rA;
        float sB = k1 ? pw : py;
        float rB = __shfl_xor_sync(FULL, sB, 1);
        float v1 = (k1 ? py : pw) + rB;
        const bool k2 = !(lane & 2);
        float sC = k2 ? v1 : v0;
        float rC = __shfl_xor_sync(FULL, sC, 2);
        float v  = (k2 ? v0 : v1) + rC;
        v += __shfl_xor_sync(FULL, v, 4);
        v += __shfl_xor_sync(FULL, v, 8);
        v += __shfl_xor_sync(FULL, v, 16);
        if (lane < 4) s_red[buf][warp * 4 + lane] = v;
        __syncthreads();
        float u = s_red[buf][lane] + s_red[buf][32 + lane];
        u += __shfl_xor_sync(FULL, u, 4);
        u += __shfl_xor_sync(FULL, u, 8);
        u += __shfl_xor_sync(FULL, u, 16);
        if (warp == 0 && lane < 4) {
            st_async_f32(buf ? p_rem1 : p_rem0, u, buf ? p_mbar1 : p_mbar0);
        }
        mbar_wait(mbar_base + (unsigned)buf * 8u, buf ? ph1 : ph0);
        float4 rem = s_rem[buf];
        if (rank == 0 && warp == 0) {
            if (lane == 1) outp[(T_ - 1) * O_ + 0] = u + rem.y;
            if (lane == 3) outp[(T_ - 1) * O_ + 1] = u + rem.w;
        }
    }

    cluster_sync();   // no CTA exits while peer may still target our SMEM
}

extern "C" void kernel_launch(void* const* d_in, const int* in_sizes, int n_in,
                              void* d_out, int out_size) {
    (void)in_sizes; (void)n_in; (void)out_size;
    const float* input    = (const float*)d_in[0];
    const float* noise    = (const float*)d_in[1];
    const float* wi       = (const float*)d_in[2];
    const float* unitwi   = (const float*)d_in[3];
    const float* m        = (const float*)d_in[4];
    const float* n        = (const float*)d_in[5];
    const float* unitm    = (const float*)d_in[6];
    const float* unitn    = (const float*)d_in[7];
    const float* wo       = (const float*)d_in[8];
    const float* h0       = (const float*)d_in[9];
    const float* unith0   = (const float*)d_in[10];
    const float* bias     = (const float*)d_in[11];
    const float* gb       = (const float*)d_in[12];
    const float* uv       = (const float*)d_in[13];
    const float* sup      = (const float*)d_in[14];
    float* out            = (float*)d_out;

    lowrank_rnn_kernel<<<2 * B_, NTHREADS>>>(input, noise, wi, unitwi, m, n,
                                             unitm, unitn, wo, h0, unith0,
                                             bias, gb, uv, sup, out);
}